// round 4
// baseline (speedup 1.0000x reference)
#include <cuda_runtime.h>
#include <cuda_fp16.h>

typedef unsigned int u32;

static constexpr int NPTS  = 1048576;
static constexpr int TILES = NPTS / 128;   // 8192
static constexpr int NBLK  = 296;          // 2 CTAs/SM * 148 SMs
static constexpr int SFSTR = 100;          // staged row stride (floats)
static constexpr int SF_BYTES = 128 * SFSTR * 4;          // 51200
static constexpr int NFRAG = 100;                         // weight fragments
static constexpr int WF_BYTES = NFRAG * 512;              // 51200
static constexpr int GEO_BYTES = 128 * 3 * 16;            // 6144
static constexpr int SMEM_TOTAL = SF_BYTES + WF_BYTES + GEO_BYTES; // 108544

// ---------------- planes transposed to (plane, H, W, C) ----------------
__device__ float g_planes[3 * 256 * 256 * 32];

__global__ void transpose_kernel(const float* __restrict__ pxy,
                                 const float* __restrict__ pxz,
                                 const float* __restrict__ pyz) {
    __shared__ float tile[32][33];
    const float* src = blockIdx.z == 0 ? pxy : (blockIdx.z == 1 ? pxz : pyz);
    const int x0 = blockIdx.x * 32;
    const int y  = blockIdx.y;
    tile[threadIdx.y][threadIdx.x] = src[threadIdx.y * 65536 + y * 256 + x0 + threadIdx.x];
    __syncthreads();
    g_planes[((blockIdx.z * 256 + y) * 256 + (x0 + threadIdx.y)) * 32 + threadIdx.x] =
        tile[threadIdx.x][threadIdx.y];
}

// ---------------- helpers ----------------
__device__ __forceinline__ void split2(float a, float b, u32& hi, u32& lo) {
    half2 h = __floats2half2_rn(a, b);
    float2 hf = __half22float2(h);
    half2 l = __floats2half2_rn(a - hf.x, b - hf.y);
    hi = *reinterpret_cast<u32*>(&h);
    lo = *reinterpret_cast<u32*>(&l);
}

__device__ __forceinline__ void mma16(float* d, const u32* a, u32 b0, u32 b1) {
    asm volatile("mma.sync.aligned.m16n8k16.row.col.f32.f16.f16.f32 "
                 "{%0,%1,%2,%3}, {%4,%5,%6,%7}, {%8,%9}, {%0,%1,%2,%3};"
                 : "+f"(d[0]), "+f"(d[1]), "+f"(d[2]), "+f"(d[3])
                 : "r"(a[0]), "r"(a[1]), "r"(a[2]), "r"(a[3]), "r"(b0), "r"(b1));
}

// one mma-triple: D += (Ahi+Alo)(Bhi+Blo) - Alo*Blo (negligible)
__device__ __forceinline__ void mma3(float* d, const u32* ah, const u32* al, uint4 B) {
    mma16(d, ah, B.x, B.y);
    mma16(d, al, B.x, B.y);
    mma16(d, ah, B.z, B.w);
}

__device__ __forceinline__ void build_a_relu(const float* s0, const float* s1,
                                             u32* ah, u32* al) {
    split2(fmaxf(s0[0], 0.f), fmaxf(s0[1], 0.f), ah[0], al[0]);
    split2(fmaxf(s0[2], 0.f), fmaxf(s0[3], 0.f), ah[1], al[1]);
    split2(fmaxf(s1[0], 0.f), fmaxf(s1[1], 0.f), ah[2], al[2]);
    split2(fmaxf(s1[2], 0.f), fmaxf(s1[3], 0.f), ah[3], al[3]);
}
__device__ __forceinline__ void build_a(const float* s0, const float* s1,
                                        u32* ah, u32* al) {
    split2(s0[0], s0[1], ah[0], al[0]);
    split2(s0[2], s0[3], ah[1], al[1]);
    split2(s1[0], s1[1], ah[2], al[2]);
    split2(s1[2], s1[3], ah[3], al[3]);
}

__device__ __forceinline__ float sigm(float x) { return 1.f / (1.f + __expf(-x)); }

// weight fragment table layout (frag index -> layer tile):
//  [0,48):  W1 (96,64)   kt=f/8, nt=f%8
//  [48,56): W2 (64,16)   kt=(f-48)/2, nt=(f-48)%2
//  [56,64): W3'(16,64)   kt=0, nt=f-56   (row0 = 0: sigma column masked)
//  [64,96): W4 (64,64)   kt=(f-64)/8, nt=(f-64)%8
//  [96,100):W5'(64,8)    kt=f-96, nt=0   (cols>=3 = 0)

__global__ __launch_bounds__(128)
void nerf_mma(const float* __restrict__ xin,
              const float* __restrict__ center,
              const float* __restrict__ scale,
              const float* __restrict__ w1,
              const float* __restrict__ w2,
              const float* __restrict__ w3,
              const float* __restrict__ w4,
              const float* __restrict__ w5,
              float* __restrict__ out) {
    extern __shared__ __align__(16) char smem[];
    float* sf   = (float*)smem;
    uint4* swf  = (uint4*)(smem + SF_BYTES);
    uint4* sgeo = (uint4*)(smem + SF_BYTES + WF_BYTES);

    const int tid  = threadIdx.x;
    const int wid  = tid >> 5;
    const int lane = tid & 31;
    const int g  = lane >> 2;        // fragment row group
    const int t2 = (lane & 3) * 2;   // fragment col pair

    // ---- build weight fragments (hi/lo fp16, fragment order) ----
    for (int f = wid; f < NFRAG; f += 4) {
        float v0, v1, v2, v3;
        if (f < 48) {
            int kt = f >> 3, nt = f & 7;
            int ka = kt * 16 + t2, n = nt * 8 + g;
            v0 = w1[ka * 64 + n];       v1 = w1[(ka + 1) * 64 + n];
            v2 = w1[(ka + 8) * 64 + n]; v3 = w1[(ka + 9) * 64 + n];
        } else if (f < 56) {
            int q = f - 48, kt = q >> 1, nt = q & 1;
            int ka = kt * 16 + t2, n = nt * 8 + g;
            v0 = w2[ka * 16 + n];       v1 = w2[(ka + 1) * 16 + n];
            v2 = w2[(ka + 8) * 16 + n]; v3 = w2[(ka + 9) * 16 + n];
        } else if (f < 64) {
            int nt = f - 56;
            int ka = t2, n = nt * 8 + g;
            v0 = (ka == 0) ? 0.f : w3[(ka - 1) * 64 + n];
            v1 = w3[ka * 64 + n];
            v2 = w3[(ka + 7) * 64 + n];
            v3 = w3[(ka + 8) * 64 + n];
        } else if (f < 96) {
            int q = f - 64, kt = q >> 3, nt = q & 7;
            int ka = kt * 16 + t2, n = nt * 8 + g;
            v0 = w4[ka * 64 + n];       v1 = w4[(ka + 1) * 64 + n];
            v2 = w4[(ka + 8) * 64 + n]; v3 = w4[(ka + 9) * 64 + n];
        } else {
            int kt = f - 96;
            int ka = kt * 16 + t2, n = g;
            v0 = (n < 3) ? w5[ka * 3 + n] : 0.f;
            v1 = (n < 3) ? w5[(ka + 1) * 3 + n] : 0.f;
            v2 = (n < 3) ? w5[(ka + 8) * 3 + n] : 0.f;
            v3 = (n < 3) ? w5[(ka + 9) * 3 + n] : 0.f;
        }
        uint4 q;
        split2(v0, v1, q.x, q.z);
        split2(v2, v3, q.y, q.w);
        swf[f * 32 + lane] = q;
    }
    __syncthreads();

    const float c0 = center[0], c1 = center[1], c2 = center[2];
    const float s0 = scale[0],  s1 = scale[1],  s2 = scale[2];
    const int rw = wid * 32;
    const int cc = lane >> 3;        // corner index for coop gather
    const int jj = lane & 7;         // chunk index

    for (int tile = blockIdx.x; tile < TILES; tile += gridDim.x) {
        const int pid = tile * 128 + tid;
        const float px = xin[3 * pid + 0];
        const float py = xin[3 * pid + 1];
        const float pz = xin[3 * pid + 2];

        float vx = fminf(fmaxf((px - c0) / s0 + 0.5f, 0.f), 1.f) * 255.f;
        float vy = fminf(fmaxf((py - c1) / s1 + 0.5f, 0.f), 1.f) * 255.f;
        float vz = fminf(fmaxf((pz - c2) / s2 + 0.5f, 0.f), 1.f) * 255.f;
        float flx = floorf(vx), fly = floorf(vy), flz = floorf(vz);
        float fx = vx - flx, fy = vy - fly, fz = vz - flz;
        int x0i = (int)flx, x1i = min(x0i + 1, 255);
        int y0i = (int)fly, y1i = min(y0i + 1, 255);
        int z0i = (int)flz, z1i = min(z0i + 1, 255);

        // ---- phase A: stage per-point geometry (packed) ----
        {
            const float fus[3] = {fx, fx, fy};
            const float fvs[3] = {fy, fz, fz};
            const int u0s[3] = {x0i, x0i, y0i}, u1s[3] = {x1i, x1i, y1i};
            const int v0s[3] = {y0i, z0i, z0i}, v1s[3] = {y1i, z1i, z1i};
#pragma unroll
            for (int q = 0; q < 3; q++) {
                u32 base = (u32)q * 2097152u + (u32)((v0s[q] * 256 + u0s[q]) * 32);
                u32 meta = base | ((u1s[q] > u0s[q]) ? (1u << 30) : 0u)
                                | ((v1s[q] > v0s[q]) ? (1u << 31) : 0u);
                uint4 G;
                G.x = meta;
                G.y = __float_as_uint(fus[q]);
                G.z = __float_as_uint(fvs[q]);
                G.w = 0u;
                sgeo[tid * 3 + q] = G;
            }
        }
        __syncwarp();

        // ---- phase B: cooperative gather (1 point-plane per LDG, 4 lines) ----
#pragma unroll 2
        for (int p = 0; p < 32; p++) {
#pragma unroll
            for (int q = 0; q < 3; q++) {
                uint4 G = sgeo[(rw + p) * 3 + q];          // broadcast LDS.128
                u32 meta = G.x;
                float fu = __uint_as_float(G.y);
                float fv = __uint_as_float(G.z);
                u32 off = (meta & 0x00FFFFFFu) + (u32)(jj * 4);
                if (cc & 1) off += ((meta >> 30) & 1u) * 32u;
                if (cc & 2) off += (meta >> 31) * 8192u;
                float4 f = *(const float4*)(g_planes + off);
                float wu = (cc & 1) ? fu : 1.f - fu;
                float wv = (cc & 2) ? fv : 1.f - fv;
                float w = wu * wv;
                f.x *= w; f.y *= w; f.z *= w; f.w *= w;
                f.x += __shfl_xor_sync(0xffffffffu, f.x, 8);
                f.y += __shfl_xor_sync(0xffffffffu, f.y, 8);
                f.z += __shfl_xor_sync(0xffffffffu, f.z, 8);
                f.w += __shfl_xor_sync(0xffffffffu, f.w, 8);
                f.x += __shfl_xor_sync(0xffffffffu, f.x, 16);
                f.y += __shfl_xor_sync(0xffffffffu, f.y, 16);
                f.z += __shfl_xor_sync(0xffffffffu, f.z, 16);
                f.w += __shfl_xor_sync(0xffffffffu, f.w, 16);
                if (lane < 8)
                    *(float4*)&sf[(rw + p) * SFSTR + q * 32 + jj * 4] = f;
            }
        }
        __syncwarp();

        // ---- per m16-tile MLP ----
#pragma unroll
        for (int mt = 0; mt < 2; mt++) {
            // L1: [16x96] @ W1 -> D1[8]
            float D1[8][4];
#pragma unroll
            for (int n = 0; n < 8; n++)
#pragma unroll
                for (int q = 0; q < 4; q++) D1[n][q] = 0.f;
#pragma unroll
            for (int kt = 0; kt < 6; kt++) {
                u32 ah[4], al[4];
                const float* rp = &sf[(rw + mt * 16 + g) * SFSTR + kt * 16 + t2];
                float2 p0 = *(const float2*)rp;
                float2 p1 = *(const float2*)(rp + 8 * SFSTR);
                float2 p2 = *(const float2*)(rp + 8);
                float2 p3 = *(const float2*)(rp + 8 * SFSTR + 8);
                split2(p0.x, p0.y, ah[0], al[0]);
                split2(p1.x, p1.y, ah[1], al[1]);
                split2(p2.x, p2.y, ah[2], al[2]);
                split2(p3.x, p3.y, ah[3], al[3]);
#pragma unroll
                for (int nt = 0; nt < 8; nt++)
                    mma3(D1[nt], ah, al, swf[(kt * 8 + nt) * 32 + lane]);
            }

            // L2
            float D2[2][4];
#pragma unroll
            for (int n = 0; n < 2; n++)
#pragma unroll
                for (int q = 0; q < 4; q++) D2[n][q] = 0.f;
#pragma unroll
            for (int kt = 0; kt < 4; kt++) {
                u32 ah[4], al[4];
                build_a_relu(D1[2 * kt], D1[2 * kt + 1], ah, al);
#pragma unroll
                for (int nt = 0; nt < 2; nt++)
                    mma3(D2[nt], ah, al, swf[(48 + kt * 2 + nt) * 32 + lane]);
            }

            // L3
            float D3[8][4];
#pragma unroll
            for (int n = 0; n < 8; n++)
#pragma unroll
                for (int q = 0; q < 4; q++) D3[n][q] = 0.f;
            {
                u32 ah[4], al[4];
                build_a(D2[0], D2[1], ah, al);
#pragma unroll
                for (int nt = 0; nt < 8; nt++)
                    mma3(D3[nt], ah, al, swf[(56 + nt) * 32 + lane]);
            }

            // L4
            float D4[8][4];
#pragma unroll
            for (int n = 0; n < 8; n++)
#pragma unroll
                for (int q = 0; q < 4; q++) D4[n][q] = 0.f;
#pragma unroll
            for (int kt = 0; kt < 4; kt++) {
                u32 ah[4], al[4];
                build_a_relu(D3[2 * kt], D3[2 * kt + 1], ah, al);
#pragma unroll
                for (int nt = 0; nt < 8; nt++)
                    mma3(D4[nt], ah, al, swf[(64 + kt * 8 + nt) * 32 + lane]);
            }

            // L5
            float D5[4] = {0.f, 0.f, 0.f, 0.f};
#pragma unroll
            for (int kt = 0; kt < 4; kt++) {
                u32 ah[4], al[4];
                build_a_relu(D4[2 * kt], D4[2 * kt + 1], ah, al);
                mma3(D5, ah, al, swf[(96 + kt) * 32 + lane]);
            }

            // epilogue
            const int r0 = tile * 128 + rw + mt * 16 + g;
            const int r1 = r0 + 8;
            const int lm = lane & 3;
            if (lm == 0) {
                out[3 * r0 + 0] = sigm(D5[0]);
                out[3 * r0 + 1] = sigm(D5[1]);
                out[3 * r1 + 0] = sigm(D5[2]);
                out[3 * r1 + 1] = sigm(D5[3]);
                out[3 * NPTS + r0] = D2[0][0];
                out[3 * NPTS + r1] = D2[0][2];
            } else if (lm == 1) {
                out[3 * r0 + 2] = sigm(D5[0]);
                out[3 * r1 + 2] = sigm(D5[2]);
            }
        }
    }
}

extern "C" void kernel_launch(void* const* d_in, const int* in_sizes, int n_in,
                              void* d_out, int out_size) {
    const float* x      = (const float*)d_in[0];
    const float* pxy    = (const float*)d_in[2];
    const float* pxz    = (const float*)d_in[3];
    const float* pyz    = (const float*)d_in[4];
    const float* center = (const float*)d_in[5];
    const float* scale  = (const float*)d_in[6];
    const float* w1     = (const float*)d_in[7];
    const float* w2     = (const float*)d_in[8];
    const float* w3     = (const float*)d_in[9];
    const float* w4     = (const float*)d_in[10];
    const float* w5     = (const float*)d_in[11];

    cudaFuncSetAttribute(nerf_mma, cudaFuncAttributeMaxDynamicSharedMemorySize, SMEM_TOTAL);

    dim3 tb(32, 32), tg(8, 256, 3);
    transpose_kernel<<<tg, tb>>>(pxy, pxz, pyz);
    nerf_mma<<<NBLK, 128, SMEM_TOTAL>>>(x, center, scale, w1, w2, w3, w4, w5, (float*)d_out);
}

// round 5
// speedup vs baseline: 1.4468x; 1.4468x over previous
#include <cuda_runtime.h>
#include <cuda_fp16.h>

typedef unsigned int u32;

static constexpr int NPTS  = 1048576;
static constexpr int TILES = NPTS / 128;   // 8192
static constexpr int NBLK  = 296;          // 2 CTAs/SM * 148 SMs
static constexpr int SFSTR = 100;          // staged row stride (floats)
static constexpr int SF_BYTES = 128 * SFSTR * 4;          // 51200
static constexpr int NFRAG = 100;                         // weight fragments
static constexpr int WF_BYTES = NFRAG * 512;              // 51200
static constexpr int GEO_BYTES = 128 * 3 * 16;            // 6144
static constexpr int SMEM_TOTAL = SF_BYTES + WF_BYTES + GEO_BYTES; // 108544

// ---------------- planes transposed to (plane, H, W, C) ----------------
__device__ float g_planes[3 * 256 * 256 * 32];

__global__ void transpose_kernel(const float* __restrict__ pxy,
                                 const float* __restrict__ pxz,
                                 const float* __restrict__ pyz) {
    __shared__ float tile[32][33];
    const float* src = blockIdx.z == 0 ? pxy : (blockIdx.z == 1 ? pxz : pyz);
    const int x0 = blockIdx.x * 32;
    const int y  = blockIdx.y;
    tile[threadIdx.y][threadIdx.x] = src[threadIdx.y * 65536 + y * 256 + x0 + threadIdx.x];
    __syncthreads();
    g_planes[((blockIdx.z * 256 + y) * 256 + (x0 + threadIdx.y)) * 32 + threadIdx.x] =
        tile[threadIdx.x][threadIdx.y];
}

// ---------------- helpers ----------------
__device__ __forceinline__ void split2(float a, float b, u32& hi, u32& lo) {
    half2 h = __floats2half2_rn(a, b);
    float2 hf = __half22float2(h);
    half2 l = __floats2half2_rn(a - hf.x, b - hf.y);
    hi = *reinterpret_cast<u32*>(&h);
    lo = *reinterpret_cast<u32*>(&l);
}

__device__ __forceinline__ void mma16(float* d, const u32* a, u32 b0, u32 b1) {
    asm volatile("mma.sync.aligned.m16n8k16.row.col.f32.f16.f16.f32 "
                 "{%0,%1,%2,%3}, {%4,%5,%6,%7}, {%8,%9}, {%0,%1,%2,%3};"
                 : "+f"(d[0]), "+f"(d[1]), "+f"(d[2]), "+f"(d[3])
                 : "r"(a[0]), "r"(a[1]), "r"(a[2]), "r"(a[3]), "r"(b0), "r"(b1));
}

// one mma-triple: D += (Ahi+Alo)(Bhi+Blo) - Alo*Blo (negligible)
__device__ __forceinline__ void mma3(float* d, const u32* ah, const u32* al, uint4 B) {
    mma16(d, ah, B.x, B.y);
    mma16(d, al, B.x, B.y);
    mma16(d, ah, B.z, B.w);
}

__device__ __forceinline__ void build_a_relu(const float* s0, const float* s1,
                                             u32* ah, u32* al) {
    split2(fmaxf(s0[0], 0.f), fmaxf(s0[1], 0.f), ah[0], al[0]);
    split2(fmaxf(s0[2], 0.f), fmaxf(s0[3], 0.f), ah[1], al[1]);
    split2(fmaxf(s1[0], 0.f), fmaxf(s1[1], 0.f), ah[2], al[2]);
    split2(fmaxf(s1[2], 0.f), fmaxf(s1[3], 0.f), ah[3], al[3]);
}
__device__ __forceinline__ void build_a(const float* s0, const float* s1,
                                        u32* ah, u32* al) {
    split2(s0[0], s0[1], ah[0], al[0]);
    split2(s0[2], s0[3], ah[1], al[1]);
    split2(s1[0], s1[1], ah[2], al[2]);
    split2(s1[2], s1[3], ah[3], al[3]);
}

__device__ __forceinline__ float sigm(float x) { return 1.f / (1.f + __expf(-x)); }

// weight fragment table layout (frag index -> layer tile):
//  [0,48):  W1 (96,64)   kt=f/8, nt=f%8
//  [48,56): W2 (64,16)   kt=(f-48)/2, nt=(f-48)%2
//  [56,64): W3'(16,64)   kt=0, nt=f-56   (row0 = 0: sigma column masked)
//  [64,96): W4 (64,64)   kt=(f-64)/8, nt=(f-64)%8
//  [96,100):W5'(64,8)    kt=f-96, nt=0   (cols>=3 = 0)

__global__ __launch_bounds__(128)
void nerf_mma(const float* __restrict__ xin,
              const float* __restrict__ center,
              const float* __restrict__ scale,
              const float* __restrict__ w1,
              const float* __restrict__ w2,
              const float* __restrict__ w3,
              const float* __restrict__ w4,
              const float* __restrict__ w5,
              float* __restrict__ out) {
    extern __shared__ __align__(16) char smem[];
    float* sf   = (float*)smem;
    uint4* swf  = (uint4*)(smem + SF_BYTES);
    uint4* sgeo = (uint4*)(smem + SF_BYTES + WF_BYTES);

    const int tid  = threadIdx.x;
    const int wid  = tid >> 5;
    const int lane = tid & 31;
    const int g  = lane >> 2;        // fragment row group
    const int t2 = (lane & 3) * 2;   // fragment col pair

    // ---- build weight fragments (hi/lo fp16, fragment order) ----
    for (int f = wid; f < NFRAG; f += 4) {
        float v0, v1, v2, v3;
        if (f < 48) {
            int kt = f >> 3, nt = f & 7;
            int ka = kt * 16 + t2, n = nt * 8 + g;
            v0 = w1[ka * 64 + n];       v1 = w1[(ka + 1) * 64 + n];
            v2 = w1[(ka + 8) * 64 + n]; v3 = w1[(ka + 9) * 64 + n];
        } else if (f < 56) {
            int q = f - 48, kt = q >> 1, nt = q & 1;
            int ka = kt * 16 + t2, n = nt * 8 + g;
            v0 = w2[ka * 16 + n];       v1 = w2[(ka + 1) * 16 + n];
            v2 = w2[(ka + 8) * 16 + n]; v3 = w2[(ka + 9) * 16 + n];
        } else if (f < 64) {
            int nt = f - 56;
            int ka = t2, n = nt * 8 + g;
            v0 = (ka == 0) ? 0.f : w3[(ka - 1) * 64 + n];
            v1 = w3[ka * 64 + n];
            v2 = w3[(ka + 7) * 64 + n];
            v3 = w3[(ka + 8) * 64 + n];
        } else if (f < 96) {
            int q = f - 64, kt = q >> 3, nt = q & 7;
            int ka = kt * 16 + t2, n = nt * 8 + g;
            v0 = w4[ka * 64 + n];       v1 = w4[(ka + 1) * 64 + n];
            v2 = w4[(ka + 8) * 64 + n]; v3 = w4[(ka + 9) * 64 + n];
        } else {
            int kt = f - 96;
            int ka = kt * 16 + t2, n = g;
            v0 = (n < 3) ? w5[ka * 3 + n] : 0.f;
            v1 = (n < 3) ? w5[(ka + 1) * 3 + n] : 0.f;
            v2 = (n < 3) ? w5[(ka + 8) * 3 + n] : 0.f;
            v3 = (n < 3) ? w5[(ka + 9) * 3 + n] : 0.f;
        }
        uint4 q;
        split2(v0, v1, q.x, q.z);
        split2(v2, v3, q.y, q.w);
        swf[f * 32 + lane] = q;
    }
    __syncthreads();

    const float c0 = center[0], c1 = center[1], c2 = center[2];
    const float s0 = scale[0],  s1 = scale[1],  s2 = scale[2];
    const int rw = wid * 32;
    const int cc = lane >> 3;        // corner index for coop gather
    const int jj = lane & 7;         // chunk index
    const u32 cu = (cc & 1) ? 1u : 0u;   // corner u-select
    const u32 cv = (cc & 2) ? 1u : 0u;   // corner v-select

    for (int tile = blockIdx.x; tile < TILES; tile += gridDim.x) {
        const int pid = tile * 128 + tid;
        const float px = xin[3 * pid + 0];
        const float py = xin[3 * pid + 1];
        const float pz = xin[3 * pid + 2];

        float vx = fminf(fmaxf((px - c0) / s0 + 0.5f, 0.f), 1.f) * 255.f;
        float vy = fminf(fmaxf((py - c1) / s1 + 0.5f, 0.f), 1.f) * 255.f;
        float vz = fminf(fmaxf((pz - c2) / s2 + 0.5f, 0.f), 1.f) * 255.f;
        float flx = floorf(vx), fly = floorf(vy), flz = floorf(vz);
        float fx = vx - flx, fy = vy - fly, fz = vz - flz;
        int x0i = (int)flx, x1i = min(x0i + 1, 255);
        int y0i = (int)fly, y1i = min(y0i + 1, 255);
        int z0i = (int)flz, z1i = min(z0i + 1, 255);

        // ---- phase A: stage per-point geometry (packed) ----
        {
            const float fus[3] = {fx, fx, fy};
            const float fvs[3] = {fy, fz, fz};
            const int u0s[3] = {x0i, x0i, y0i}, u1s[3] = {x1i, x1i, y1i};
            const int v0s[3] = {y0i, z0i, z0i}, v1s[3] = {y1i, z1i, z1i};
#pragma unroll
            for (int q = 0; q < 3; q++) {
                u32 base = (u32)q * 2097152u + (u32)((v0s[q] * 256 + u0s[q]) * 32);
                u32 meta = base | ((u1s[q] > u0s[q]) ? (1u << 30) : 0u)
                                | ((v1s[q] > v0s[q]) ? (1u << 31) : 0u);
                uint4 G;
                G.x = meta;
                G.y = __float_as_uint(fus[q]);
                G.z = __float_as_uint(fvs[q]);
                G.w = 0u;
                sgeo[tid * 3 + q] = G;
            }
        }
        __syncwarp();

        // ---- phase B: batched cooperative gather (MLP=8) ----
#pragma unroll
        for (int q = 0; q < 3; q++) {
#pragma unroll
            for (int b = 0; b < 4; b++) {
                u32 off[8];
                float wgt[8];
#pragma unroll
                for (int j = 0; j < 8; j++) {
                    uint4 G = sgeo[(rw + b * 8 + j) * 3 + q];   // broadcast LDS.128
                    u32 meta = G.x;
                    float fu = __uint_as_float(G.y);
                    float fv = __uint_as_float(G.z);
                    u32 o = (meta & 0x00FFFFFFu) + (u32)(jj * 4);
                    o += cu * (((meta >> 30) & 1u) * 32u);
                    o += cv * ((meta >> 31) * 8192u);
                    off[j] = o;
                    float wu = cu ? fu : 1.f - fu;
                    float wv = cv ? fv : 1.f - fv;
                    wgt[j] = wu * wv;
                }
                float4 f[8];
#pragma unroll
                for (int j = 0; j < 8; j++)
                    f[j] = *(const float4*)(g_planes + off[j]);
#pragma unroll
                for (int j = 0; j < 8; j++) {
                    float4 v = f[j];
                    float w = wgt[j];
                    v.x *= w; v.y *= w; v.z *= w; v.w *= w;
                    v.x += __shfl_xor_sync(0xffffffffu, v.x, 8);
                    v.y += __shfl_xor_sync(0xffffffffu, v.y, 8);
                    v.z += __shfl_xor_sync(0xffffffffu, v.z, 8);
                    v.w += __shfl_xor_sync(0xffffffffu, v.w, 8);
                    v.x += __shfl_xor_sync(0xffffffffu, v.x, 16);
                    v.y += __shfl_xor_sync(0xffffffffu, v.y, 16);
                    v.z += __shfl_xor_sync(0xffffffffu, v.z, 16);
                    v.w += __shfl_xor_sync(0xffffffffu, v.w, 16);
                    if (lane < 8)
                        *(float4*)&sf[(rw + b * 8 + j) * SFSTR + q * 32 + jj * 4] = v;
                }
            }
        }
        __syncwarp();

        // ---- per m16-tile MLP ----
#pragma unroll
        for (int mt = 0; mt < 2; mt++) {
            // L1: [16x96] @ W1 -> D1[8]
            float D1[8][4];
#pragma unroll
            for (int n = 0; n < 8; n++)
#pragma unroll
                for (int q = 0; q < 4; q++) D1[n][q] = 0.f;
#pragma unroll
            for (int kt = 0; kt < 6; kt++) {
                u32 ah[4], al[4];
                const float* rp = &sf[(rw + mt * 16 + g) * SFSTR + kt * 16 + t2];
                float2 p0 = *(const float2*)rp;
                float2 p1 = *(const float2*)(rp + 8 * SFSTR);
                float2 p2 = *(const float2*)(rp + 8);
                float2 p3 = *(const float2*)(rp + 8 * SFSTR + 8);
                split2(p0.x, p0.y, ah[0], al[0]);
                split2(p1.x, p1.y, ah[1], al[1]);
                split2(p2.x, p2.y, ah[2], al[2]);
                split2(p3.x, p3.y, ah[3], al[3]);
#pragma unroll
                for (int nt = 0; nt < 8; nt++)
                    mma3(D1[nt], ah, al, swf[(kt * 8 + nt) * 32 + lane]);
            }

            // L2
            float D2[2][4];
#pragma unroll
            for (int n = 0; n < 2; n++)
#pragma unroll
                for (int q = 0; q < 4; q++) D2[n][q] = 0.f;
#pragma unroll
            for (int kt = 0; kt < 4; kt++) {
                u32 ah[4], al[4];
                build_a_relu(D1[2 * kt], D1[2 * kt + 1], ah, al);
#pragma unroll
                for (int nt = 0; nt < 2; nt++)
                    mma3(D2[nt], ah, al, swf[(48 + kt * 2 + nt) * 32 + lane]);
            }

            // L3
            float D3[8][4];
#pragma unroll
            for (int n = 0; n < 8; n++)
#pragma unroll
                for (int q = 0; q < 4; q++) D3[n][q] = 0.f;
            {
                u32 ah[4], al[4];
                build_a(D2[0], D2[1], ah, al);
#pragma unroll
                for (int nt = 0; nt < 8; nt++)
                    mma3(D3[nt], ah, al, swf[(56 + nt) * 32 + lane]);
            }

            // L4
            float D4[8][4];
#pragma unroll
            for (int n = 0; n < 8; n++)
#pragma unroll
                for (int q = 0; q < 4; q++) D4[n][q] = 0.f;
#pragma unroll
            for (int kt = 0; kt < 4; kt++) {
                u32 ah[4], al[4];
                build_a_relu(D3[2 * kt], D3[2 * kt + 1], ah, al);
#pragma unroll
                for (int nt = 0; nt < 8; nt++)
                    mma3(D4[nt], ah, al, swf[(64 + kt * 8 + nt) * 32 + lane]);
            }

            // L5
            float D5[4] = {0.f, 0.f, 0.f, 0.f};
#pragma unroll
            for (int kt = 0; kt < 4; kt++) {
                u32 ah[4], al[4];
                build_a_relu(D4[2 * kt], D4[2 * kt + 1], ah, al);
                mma3(D5, ah, al, swf[(96 + kt) * 32 + lane]);
            }

            // epilogue
            const int r0 = tile * 128 + rw + mt * 16 + g;
            const int r1 = r0 + 8;
            const int lm = lane & 3;
            if (lm == 0) {
                out[3 * r0 + 0] = sigm(D5[0]);
                out[3 * r0 + 1] = sigm(D5[1]);
                out[3 * r1 + 0] = sigm(D5[2]);
                out[3 * r1 + 1] = sigm(D5[3]);
                out[3 * NPTS + r0] = D2[0][0];
                out[3 * NPTS + r1] = D2[0][2];
            } else if (lm == 1) {
                out[3 * r0 + 2] = sigm(D5[0]);
                out[3 * r1 + 2] = sigm(D5[2]);
            }
        }
    }
}

extern "C" void kernel_launch(void* const* d_in, const int* in_sizes, int n_in,
                              void* d_out, int out_size) {
    const float* x      = (const float*)d_in[0];
    const float* pxy    = (const float*)d_in[2];
    const float* pxz    = (const float*)d_in[3];
    const float* pyz    = (const float*)d_in[4];
    const float* center = (const float*)d_in[5];
    const float* scale  = (const float*)d_in[6];
    const float* w1     = (const float*)d_in[7];
    const float* w2     = (const float*)d_in[8];
    const float* w3     = (const float*)d_in[9];
    const float* w4     = (const float*)d_in[10];
    const float* w5     = (const float*)d_in[11];

    cudaFuncSetAttribute(nerf_mma, cudaFuncAttributeMaxDynamicSharedMemorySize, SMEM_TOTAL);

    dim3 tb(32, 32), tg(8, 256, 3);
    transpose_kernel<<<tg, tb>>>(pxy, pxz, pyz);
    nerf_mma<<<NBLK, 128, SMEM_TOTAL>>>(x, center, scale, w1, w2, w3, w4, w5, (float*)d_out);
}

// round 6
// speedup vs baseline: 2.6790x; 1.8518x over previous
#include <cuda_runtime.h>
#include <cuda_fp16.h>

typedef unsigned int u32;

static constexpr int NPTS  = 1048576;
static constexpr int TPB   = 256;
static constexpr int TILE_PTS = 256;
static constexpr int TILES = NPTS / TILE_PTS;  // 4096
static constexpr int NBLK  = 296;              // 2 CTAs/SM * 148 SMs
static constexpr int SFSTR = 100;              // staged row stride (floats)
static constexpr int SF_BYTES = 128 * SFSTR * 4;          // 51200 (8 warps x 16 rows)
static constexpr int NFRAG = 100;                         // weight fragments
static constexpr int WF_BYTES = NFRAG * 512;              // 51200
static constexpr int SMEM_TOTAL = SF_BYTES + WF_BYTES;    // 102400

// ---------------- planes transposed to (plane, H, W, C) ----------------
__device__ float g_planes[3 * 256 * 256 * 32];

__global__ void transpose_kernel(const float* __restrict__ pxy,
                                 const float* __restrict__ pxz,
                                 const float* __restrict__ pyz) {
    __shared__ float tile[32][33];
    const float* src = blockIdx.z == 0 ? pxy : (blockIdx.z == 1 ? pxz : pyz);
    const int x0 = blockIdx.x * 32;
    const int y  = blockIdx.y;
    tile[threadIdx.y][threadIdx.x] = src[threadIdx.y * 65536 + y * 256 + x0 + threadIdx.x];
    __syncthreads();
    g_planes[((blockIdx.z * 256 + y) * 256 + (x0 + threadIdx.y)) * 32 + threadIdx.x] =
        tile[threadIdx.x][threadIdx.y];
}

// ---------------- helpers ----------------
__device__ __forceinline__ void split2(float a, float b, u32& hi, u32& lo) {
    half2 h = __floats2half2_rn(a, b);
    float2 hf = __half22float2(h);
    half2 l = __floats2half2_rn(a - hf.x, b - hf.y);
    hi = *reinterpret_cast<u32*>(&h);
    lo = *reinterpret_cast<u32*>(&l);
}

__device__ __forceinline__ void mma16(float* d, const u32* a, u32 b0, u32 b1) {
    asm volatile("mma.sync.aligned.m16n8k16.row.col.f32.f16.f16.f32 "
                 "{%0,%1,%2,%3}, {%4,%5,%6,%7}, {%8,%9}, {%0,%1,%2,%3};"
                 : "+f"(d[0]), "+f"(d[1]), "+f"(d[2]), "+f"(d[3])
                 : "r"(a[0]), "r"(a[1]), "r"(a[2]), "r"(a[3]), "r"(b0), "r"(b1));
}

// one mma-triple: D += (Ahi+Alo)(Bhi+Blo) - Alo*Blo (negligible)
__device__ __forceinline__ void mma3(float* d, const u32* ah, const u32* al, uint4 B) {
    mma16(d, ah, B.x, B.y);
    mma16(d, al, B.x, B.y);
    mma16(d, ah, B.z, B.w);
}

__device__ __forceinline__ void build_a_relu(const float* s0, const float* s1,
                                             u32* ah, u32* al) {
    split2(fmaxf(s0[0], 0.f), fmaxf(s0[1], 0.f), ah[0], al[0]);
    split2(fmaxf(s0[2], 0.f), fmaxf(s0[3], 0.f), ah[1], al[1]);
    split2(fmaxf(s1[0], 0.f), fmaxf(s1[1], 0.f), ah[2], al[2]);
    split2(fmaxf(s1[2], 0.f), fmaxf(s1[3], 0.f), ah[3], al[3]);
}
__device__ __forceinline__ void build_a(const float* s0, const float* s1,
                                        u32* ah, u32* al) {
    split2(s0[0], s0[1], ah[0], al[0]);
    split2(s0[2], s0[3], ah[1], al[1]);
    split2(s1[0], s1[1], ah[2], al[2]);
    split2(s1[2], s1[3], ah[3], al[3]);
}

__device__ __forceinline__ float sigm(float x) { return 1.f / (1.f + __expf(-x)); }

// weight fragment table layout (frag index -> layer tile):
//  [0,48):  W1 (96,64)   kt=f/8, nt=f%8
//  [48,56): W2 (64,16)   kt=(f-48)/2, nt=(f-48)%2
//  [56,64): W3'(16,64)   kt=0, nt=f-56   (row0 = 0: sigma column masked)
//  [64,96): W4 (64,64)   kt=(f-64)/8, nt=(f-64)%8
//  [96,100):W5'(64,8)    kt=f-96, nt=0   (cols>=3 = 0)

__global__ __launch_bounds__(TPB, 2)
void nerf_mma(const float* __restrict__ xin,
              const float* __restrict__ center,
              const float* __restrict__ scale,
              const float* __restrict__ w1,
              const float* __restrict__ w2,
              const float* __restrict__ w3,
              const float* __restrict__ w4,
              const float* __restrict__ w5,
              float* __restrict__ out) {
    extern __shared__ __align__(16) char smem[];
    float* sf  = (float*)smem;
    uint4* swf = (uint4*)(smem + SF_BYTES);

    const int tid  = threadIdx.x;
    const int wid  = tid >> 5;
    const int lane = tid & 31;
    const int g  = lane >> 2;        // fragment row group
    const int t2 = (lane & 3) * 2;   // fragment col pair

    // ---- build weight fragments (hi/lo fp16, fragment order) ----
    for (int f = wid; f < NFRAG; f += 8) {
        float v0, v1, v2, v3;
        if (f < 48) {
            int kt = f >> 3, nt = f & 7;
            int ka = kt * 16 + t2, n = nt * 8 + g;
            v0 = w1[ka * 64 + n];       v1 = w1[(ka + 1) * 64 + n];
            v2 = w1[(ka + 8) * 64 + n]; v3 = w1[(ka + 9) * 64 + n];
        } else if (f < 56) {
            int q = f - 48, kt = q >> 1, nt = q & 1;
            int ka = kt * 16 + t2, n = nt * 8 + g;
            v0 = w2[ka * 16 + n];       v1 = w2[(ka + 1) * 16 + n];
            v2 = w2[(ka + 8) * 16 + n]; v3 = w2[(ka + 9) * 16 + n];
        } else if (f < 64) {
            int nt = f - 56;
            int ka = t2, n = nt * 8 + g;
            v0 = (ka == 0) ? 0.f : w3[(ka - 1) * 64 + n];
            v1 = w3[ka * 64 + n];
            v2 = w3[(ka + 7) * 64 + n];
            v3 = w3[(ka + 8) * 64 + n];
        } else if (f < 96) {
            int q = f - 64, kt = q >> 3, nt = q & 7;
            int ka = kt * 16 + t2, n = nt * 8 + g;
            v0 = w4[ka * 64 + n];       v1 = w4[(ka + 1) * 64 + n];
            v2 = w4[(ka + 8) * 64 + n]; v3 = w4[(ka + 9) * 64 + n];
        } else {
            int kt = f - 96;
            int ka = kt * 16 + t2, n = g;
            v0 = (n < 3) ? w5[ka * 3 + n] : 0.f;
            v1 = (n < 3) ? w5[(ka + 1) * 3 + n] : 0.f;
            v2 = (n < 3) ? w5[(ka + 8) * 3 + n] : 0.f;
            v3 = (n < 3) ? w5[(ka + 9) * 3 + n] : 0.f;
        }
        uint4 q;
        split2(v0, v1, q.x, q.z);
        split2(v2, v3, q.y, q.w);
        swf[f * 32 + lane] = q;
    }
    __syncthreads();

    const float c0 = center[0], c1 = center[1], c2 = center[2];
    const float s0 = scale[0],  s1 = scale[1],  s2 = scale[2];
    const int jj = lane & 7;     // channel chunk (4 floats)
    const int p4 = lane >> 3;    // point-in-group
    const int rwarp = wid * 16;  // this warp's staging row base

    for (int tile = blockIdx.x; tile < TILES; tile += gridDim.x) {
        const int pid = tile * TILE_PTS + wid * 32 + lane;
        const float px = xin[3 * pid + 0];
        const float py = xin[3 * pid + 1];
        const float pz = xin[3 * pid + 2];

        float vx = fminf(fmaxf((px - c0) / s0 + 0.5f, 0.f), 1.f) * 255.f;
        float vy = fminf(fmaxf((py - c1) / s1 + 0.5f, 0.f), 1.f) * 255.f;
        float vz = fminf(fmaxf((pz - c2) / s2 + 0.5f, 0.f), 1.f) * 255.f;
        float flx = floorf(vx), fly = floorf(vy), flz = floorf(vz);
        float fx = vx - flx, fy = vy - fly, fz = vz - flz;
        int x0i = (int)flx, x1i = min(x0i + 1, 255);
        int y0i = (int)fly, y1i = min(y0i + 1, 255);
        int z0i = (int)flz, z1i = min(z0i + 1, 255);

        // per-lane geometry for this lane's point (3 planes)
        u32 gm[3];
        float gfu[3], gfv[3];
        {
            const float fus[3] = {fx, fx, fy};
            const float fvs[3] = {fy, fz, fz};
            const int u0s[3] = {x0i, x0i, y0i}, u1s[3] = {x1i, x1i, y1i};
            const int v0s[3] = {y0i, z0i, z0i}, v1s[3] = {y1i, z1i, z1i};
#pragma unroll
            for (int q = 0; q < 3; q++) {
                u32 base = (u32)q * 2097152u + (u32)((v0s[q] * 256 + u0s[q]) * 32);
                gm[q] = base | ((u1s[q] > u0s[q]) ? (1u << 30) : 0u)
                             | ((v1s[q] > v0s[q]) ? (1u << 31) : 0u);
                gfu[q] = fus[q];
                gfv[q] = fvs[q];
            }
        }

        // ---- two 16-point chunks per warp: gather then MLP ----
#pragma unroll
        for (int c = 0; c < 2; c++) {
            __syncwarp();   // previous chunk's LDS reads done before restage

            // gather: lane handles (point p4 of group gq, channel chunk jj),
            // loading all 4 corners itself (4 lines per LDG warp-inst)
#pragma unroll
            for (int q = 0; q < 3; q++) {
#pragma unroll
                for (int gq = 0; gq < 4; gq++) {
                    const int src = c * 16 + gq * 4 + p4;
                    u32 meta = __shfl_sync(0xffffffffu, gm[q], src);
                    float fu = __shfl_sync(0xffffffffu, gfu[q], src);
                    float fv = __shfl_sync(0xffffffffu, gfv[q], src);
                    u32 base = (meta & 0x00FFFFFFu) + (u32)(jj * 4);
                    u32 du = ((meta >> 30) & 1u) * 32u;
                    u32 dv = (meta >> 31) * 8192u;
                    float4 f00 = *(const float4*)(g_planes + base);
                    float4 f01 = *(const float4*)(g_planes + base + du);
                    float4 f10 = *(const float4*)(g_planes + base + dv);
                    float4 f11 = *(const float4*)(g_planes + base + du + dv);
                    float w11 = fu * fv;
                    float w01 = fu - w11;
                    float w10 = fv - w11;
                    float w00 = 1.f - fu - w10;
                    float4 r;
                    r.x = f00.x * w00 + f01.x * w01 + f10.x * w10 + f11.x * w11;
                    r.y = f00.y * w00 + f01.y * w01 + f10.y * w10 + f11.y * w11;
                    r.z = f00.z * w00 + f01.z * w01 + f10.z * w10 + f11.z * w11;
                    r.w = f00.w * w00 + f01.w * w01 + f10.w * w10 + f11.w * w11;
                    *(float4*)&sf[(rwarp + gq * 4 + p4) * SFSTR + q * 32 + jj * 4] = r;
                }
            }
            __syncwarp();

            // ---- m16 MLP on this chunk ----
            // L1: [16x96] @ W1 -> D1[8]
            float D1[8][4];
#pragma unroll
            for (int n = 0; n < 8; n++)
#pragma unroll
                for (int q = 0; q < 4; q++) D1[n][q] = 0.f;
#pragma unroll
            for (int kt = 0; kt < 6; kt++) {
                u32 ah[4], al[4];
                const float* rp = &sf[(rwarp + g) * SFSTR + kt * 16 + t2];
                float2 p0 = *(const float2*)rp;
                float2 p1 = *(const float2*)(rp + 8 * SFSTR);
                float2 p2 = *(const float2*)(rp + 8);
                float2 p3 = *(const float2*)(rp + 8 * SFSTR + 8);
                split2(p0.x, p0.y, ah[0], al[0]);
                split2(p1.x, p1.y, ah[1], al[1]);
                split2(p2.x, p2.y, ah[2], al[2]);
                split2(p3.x, p3.y, ah[3], al[3]);
#pragma unroll
                for (int nt = 0; nt < 8; nt++)
                    mma3(D1[nt], ah, al, swf[(kt * 8 + nt) * 32 + lane]);
            }

            // L2
            float D2[2][4];
#pragma unroll
            for (int n = 0; n < 2; n++)
#pragma unroll
                for (int q = 0; q < 4; q++) D2[n][q] = 0.f;
#pragma unroll
            for (int kt = 0; kt < 4; kt++) {
                u32 ah[4], al[4];
                build_a_relu(D1[2 * kt], D1[2 * kt + 1], ah, al);
#pragma unroll
                for (int nt = 0; nt < 2; nt++)
                    mma3(D2[nt], ah, al, swf[(48 + kt * 2 + nt) * 32 + lane]);
            }

            // L3
            float D3[8][4];
#pragma unroll
            for (int n = 0; n < 8; n++)
#pragma unroll
                for (int q = 0; q < 4; q++) D3[n][q] = 0.f;
            {
                u32 ah[4], al[4];
                build_a(D2[0], D2[1], ah, al);
#pragma unroll
                for (int nt = 0; nt < 8; nt++)
                    mma3(D3[nt], ah, al, swf[(56 + nt) * 32 + lane]);
            }

            // L4
            float D4[8][4];
#pragma unroll
            for (int n = 0; n < 8; n++)
#pragma unroll
                for (int q = 0; q < 4; q++) D4[n][q] = 0.f;
#pragma unroll
            for (int kt = 0; kt < 4; kt++) {
                u32 ah[4], al[4];
                build_a_relu(D3[2 * kt], D3[2 * kt + 1], ah, al);
#pragma unroll
                for (int nt = 0; nt < 8; nt++)
                    mma3(D4[nt], ah, al, swf[(64 + kt * 8 + nt) * 32 + lane]);
            }

            // L5
            float D5[4] = {0.f, 0.f, 0.f, 0.f};
#pragma unroll
            for (int kt = 0; kt < 4; kt++) {
                u32 ah[4], al[4];
                build_a_relu(D4[2 * kt], D4[2 * kt + 1], ah, al);
                mma3(D5, ah, al, swf[(96 + kt) * 32 + lane]);
            }

            // epilogue
            const int r0 = tile * TILE_PTS + wid * 32 + c * 16 + g;
            const int r1 = r0 + 8;
            const int lm = lane & 3;
            if (lm == 0) {
                out[3 * r0 + 0] = sigm(D5[0]);
                out[3 * r0 + 1] = sigm(D5[1]);
                out[3 * r1 + 0] = sigm(D5[2]);
                out[3 * r1 + 1] = sigm(D5[3]);
                out[3 * NPTS + r0] = D2[0][0];
                out[3 * NPTS + r1] = D2[0][2];
            } else if (lm == 1) {
                out[3 * r0 + 2] = sigm(D5[0]);
                out[3 * r1 + 2] = sigm(D5[2]);
            }
        }
    }
}

extern "C" void kernel_launch(void* const* d_in, const int* in_sizes, int n_in,
                              void* d_out, int out_size) {
    const float* x      = (const float*)d_in[0];
    const float* pxy    = (const float*)d_in[2];
    const float* pxz    = (const float*)d_in[3];
    const float* pyz    = (const float*)d_in[4];
    const float* center = (const float*)d_in[5];
    const float* scale  = (const float*)d_in[6];
    const float* w1     = (const float*)d_in[7];
    const float* w2     = (const float*)d_in[8];
    const float* w3     = (const float*)d_in[9];
    const float* w4     = (const float*)d_in[10];
    const float* w5     = (const float*)d_in[11];

    cudaFuncSetAttribute(nerf_mma, cudaFuncAttributeMaxDynamicSharedMemorySize, SMEM_TOTAL);

    dim3 tb(32, 32), tg(8, 256, 3);
    transpose_kernel<<<tg, tb>>>(pxy, pxz, pyz);
    nerf_mma<<<NBLK, TPB, SMEM_TOTAL>>>(x, center, scale, w1, w2, w3, w4, w5, (float*)d_out);
}